// round 9
// baseline (speedup 1.0000x reference)
#include <cuda_runtime.h>
#include <cuda_fp16.h>
#include <math.h>

// ---------------------------------------------------------------------------
// NNConvNet fused GNN — R8: 64 edges per warp-pass (2 sub-tiles sharing each
// B fragment load), vectorized red.global.add.v2.f32 scatter, 10 warps/CTA.
//  per sub-tile (32 edges): phase1 ef->h1 (fp32) -> fp16 2-split A row;
//    h2 = relu(h1@W2+b2) via HMMA; h2 written back fp16; Ah fragments kept
//    in registers (A smem region reused by both sub-tiles).
//  W3 GEMM: D[64x1024] = h2 @ W3 fp16, 32 chunks of n=32 (chunk==h);
//    per chunk: 4 ldsm.x4t (double-buffered) + 32 mma (4 m-tiles);
//    epi: msg[k] += x_h * relu(acc) scalar FFMA/FMNMX.
//  scatter: 16 red.v2.f32 per thread per 8 owned rows.
// ---------------------------------------------------------------------------

#define NMAX 20000
#define EMAX 320000
#define BATCH 64
#define NWARPS 10
#define NTHREADS (NWARPS * 32)

typedef unsigned int u32;
typedef unsigned short u16;

__device__ float g_x[NMAX * 32];
__device__ float g_agg[NMAX * 32];
__device__ float g_pooled[BATCH * 32];
__device__ float g_counts[BATCH];

__constant__ int c_IDX[36] = {
    0, 1, 2,  3,  4,  5,
    1, 6, 7,  8,  9,  10,
    2, 7, 11, 12, 13, 14,
    3, 8, 12, 15, 16, 17,
    4, 9, 13, 16, 18, 19,
    5, 10,14, 17, 19, 20};

// ---------------- smem layout ----------------
// floats:
#define F_W1 0        // 160
#define F_B1 160      // 32
#define F_B2 192      // 32
#define F_B3S 224     // 1024 (ends 1248 floats = 4992 B)
// bytes:
#define OFF_W2H 4992                  // 32 rows * 80 B = 2560
#define OFF_W2L 7552                  // 2560 (ends 10112)
#define OFF_DSTS 10112                // 10 warps * 64 int = 2560 (ends 12672)
#define OFF_XS 12672                  // 10 * 64*33*4 = 84480 (ends 97152)
#define OFF_A 97152                   // 10 * 32*144 = 46080 (ends 143232)
#define OFF_B 143232                  // 32 * 2064 = 66048 (ends 209280)
#define A_STRIDE 144
#define B_STRIDE 2064
#define W2_STRIDE 80
#define SMEM_TOTAL 209280
#define XS_WARP 2112                  // floats per warp (64*33)

// ---------------- PTX helpers ----------------
__device__ __forceinline__ u32 smem_u32(const void* p) {
    u32 a;
    asm("{ .reg .u64 t; cvta.to.shared.u64 t, %1; cvt.u32.u64 %0, t; }"
        : "=r"(a) : "l"(p));
    return a;
}
__device__ __forceinline__ void ldsm_x4(u32* r, u32 addr) {
    asm volatile(
        "ldmatrix.sync.aligned.m8n8.x4.shared.b16 {%0,%1,%2,%3}, [%4];"
        : "=r"(r[0]), "=r"(r[1]), "=r"(r[2]), "=r"(r[3]) : "r"(addr));
}
__device__ __forceinline__ void ldsm_x4t(u32* r, u32 addr) {
    asm volatile(
        "ldmatrix.sync.aligned.m8n8.x4.trans.shared.b16 {%0,%1,%2,%3}, [%4];"
        : "=r"(r[0]), "=r"(r[1]), "=r"(r[2]), "=r"(r[3]) : "r"(addr));
}
__device__ __forceinline__ void mma_f16(float* d, const u32* a, u32 b0,
                                        u32 b1) {
    asm volatile(
        "mma.sync.aligned.m16n8k16.row.col.f32.f16.f16.f32 "
        "{%0,%1,%2,%3}, {%4,%5,%6,%7}, {%8,%9}, {%0,%1,%2,%3};"
        : "+f"(d[0]), "+f"(d[1]), "+f"(d[2]), "+f"(d[3])
        : "r"(a[0]), "r"(a[1]), "r"(a[2]), "r"(a[3]), "r"(b0), "r"(b1));
}
__device__ __forceinline__ void red_v2(float* ap, float m0, float m1) {
    asm volatile("red.global.add.v2.f32 [%0], {%1, %2};"
                 :: "l"(ap), "f"(m0), "f"(m1) : "memory");
}

// ---------------------------------------------------------------------------
__global__ void init_kernel(const float* __restrict__ node_attrs,
                            const float* __restrict__ embW,
                            const float* __restrict__ embB, int N) {
    int idx = blockIdx.x * blockDim.x + threadIdx.x;
    if (idx < N * 32) {
        int k = idx & 31;
        g_x[idx] = fmaf(node_attrs[idx >> 5], embW[k], embB[k]);
        g_agg[idx] = 0.f;
    }
    if (idx < BATCH * 32) g_pooled[idx] = 0.f;
    if (idx < BATCH) g_counts[idx] = 0.f;
}

// ---------------------------------------------------------------------------
__global__ void __launch_bounds__(NTHREADS, 1)
edge_kernel(const float* __restrict__ positions,
            const float* __restrict__ shifts,
            const float* __restrict__ edge_attr,
            const int* __restrict__ eidx,
            const float* __restrict__ W1, const float* __restrict__ b1,
            const float* __restrict__ W2, const float* __restrict__ b2,
            const float* __restrict__ W3, const float* __restrict__ b3,
            int E) {
    extern __shared__ float smf[];
    char* smc = (char*)smf;
    const u32 sb = smem_u32(smf);
    const int tid = threadIdx.x;
    const int lane = tid & 31;
    const int warp = tid >> 5;

    // ---- stage B = fp16(W3) in [j][n] layout ----
    for (int i = tid; i < 32768; i += NTHREADS) {
        int j = i >> 10, col = i & 1023;
        __half h = __float2half_rn(W3[i]);
        *(u16*)(smc + OFF_B + j * B_STRIDE + col * 2) = *(u16*)&h;
    }
    // ---- W2 fp16 2-split [j][n] ----
    for (int i = tid; i < 1024; i += NTHREADS) {
        int j = i >> 5, n = i & 31;
        float w = W2[i];
        __half hh = __float2half_rn(w);
        __half ll = __float2half_rn(w - __half2float(hh));
        *(u16*)(smc + OFF_W2H + j * W2_STRIDE + n * 2) = *(u16*)&hh;
        *(u16*)(smc + OFF_W2L + j * W2_STRIDE + n * 2) = *(u16*)&ll;
        smf[F_B3S + i] = b3[i];
    }
    if (tid < 160) smf[F_W1 + tid] = W1[tid];
    if (tid < 32) {
        smf[F_B1 + tid] = b1[tid];
        smf[F_B2 + tid] = b2[tid];
    }
    __syncthreads();

    const int g = lane >> 2;     // fragment row group
    const int tq = lane & 3;     // fragment col group
    char* arow_base = smc + OFF_A + (warp * 32) * A_STRIDE;
    const u32 aw = sb + OFF_A + (u32)(warp * 32) * A_STRIDE;
    float* xw = smf + (OFF_XS / 4) + warp * XS_WARP;
    int* dstw = (int*)(smc + OFF_DSTS) + warp * 64;

    const int rowoff = ((lane >> 3) & 1) * 8 + (lane & 7);
    const int colb16 = (lane >> 4) * 16;

    const int* srcp = eidx;
    const int* dstp = eidx + E;
    const int ntiles = (E + 63) >> 6;
    const int gw = blockIdx.x * NWARPS + warp;
    const int gstride = gridDim.x * NWARPS;

#define LOADB(FR, C)                                                        \
    do {                                                                    \
        u32 _bc = sb + OFF_B + (u32)((C) * 64 + colb16);                    \
        ldsm_x4t(FR[0], _bc + (u32)(rowoff * B_STRIDE));                    \
        ldsm_x4t(FR[1], _bc + (u32)((rowoff + 16) * B_STRIDE));             \
        ldsm_x4t(FR[2], _bc + 32 + (u32)(rowoff * B_STRIDE));               \
        ldsm_x4t(FR[3], _bc + 32 + (u32)((rowoff + 16) * B_STRIDE));        \
    } while (0)

#define CHUNK_BODY(BB, C)                                                   \
    do {                                                                    \
        const int _cb = (C) * 32;                                           \
        float2 bv[4];                                                       \
        _Pragma("unroll") for (int n8 = 0; n8 < 4; n8++) bv[n8] =           \
            *(const float2*)(smf + F_B3S + _cb + n8 * 8 + 2 * tq);          \
        _Pragma("unroll") for (int grp = 0; grp < 2; grp++) {               \
            float acc[2][4][4];                                             \
            _Pragma("unroll") for (int n8 = 0; n8 < 4; n8++)                \
                _Pragma("unroll") for (int mt = 0; mt < 2; mt++) {          \
                    acc[mt][n8][0] = bv[n8].x;                              \
                    acc[mt][n8][1] = bv[n8].y;                              \
                    acc[mt][n8][2] = bv[n8].x;                              \
                    acc[mt][n8][3] = bv[n8].y;                              \
                }                                                           \
            mma_f16(acc[0][0], Ah[grp][0][0], BB[0][0], BB[0][1]);          \
            mma_f16(acc[0][1], Ah[grp][0][0], BB[0][2], BB[0][3]);          \
            mma_f16(acc[1][0], Ah[grp][1][0], BB[0][0], BB[0][1]);          \
            mma_f16(acc[1][1], Ah[grp][1][0], BB[0][2], BB[0][3]);          \
            mma_f16(acc[0][2], Ah[grp][0][0], BB[2][0], BB[2][1]);          \
            mma_f16(acc[0][3], Ah[grp][0][0], BB[2][2], BB[2][3]);          \
            mma_f16(acc[1][2], Ah[grp][1][0], BB[2][0], BB[2][1]);          \
            mma_f16(acc[1][3], Ah[grp][1][0], BB[2][2], BB[2][3]);          \
            mma_f16(acc[0][0], Ah[grp][0][1], BB[1][0], BB[1][1]);          \
            mma_f16(acc[0][1], Ah[grp][0][1], BB[1][2], BB[1][3]);          \
            mma_f16(acc[1][0], Ah[grp][1][1], BB[1][0], BB[1][1]);          \
            mma_f16(acc[1][1], Ah[grp][1][1], BB[1][2], BB[1][3]);          \
            mma_f16(acc[0][2], Ah[grp][0][1], BB[3][0], BB[3][1]);          \
            mma_f16(acc[0][3], Ah[grp][0][1], BB[3][2], BB[3][3]);          \
            mma_f16(acc[1][2], Ah[grp][1][1], BB[3][0], BB[3][1]);          \
            mma_f16(acc[1][3], Ah[grp][1][1], BB[3][2], BB[3][3]);          \
            _Pragma("unroll") for (int mt = 0; mt < 2; mt++) {              \
                float x0 = xw[(grp * 32 + mt * 16 + g) * 33 + (C)];         \
                float x1 = xw[(grp * 32 + mt * 16 + 8 + g) * 33 + (C)];     \
                _Pragma("unroll") for (int t = 0; t < 4; t++) {             \
                    const float* d = acc[mt][t];                            \
                    msg[grp][mt][0][2 * t] = fmaf(                          \
                        x0, fmaxf(d[0], 0.f), msg[grp][mt][0][2 * t]);      \
                    msg[grp][mt][0][2 * t + 1] = fmaf(                      \
                        x0, fmaxf(d[1], 0.f), msg[grp][mt][0][2 * t + 1]);  \
                    msg[grp][mt][1][2 * t] = fmaf(                          \
                        x1, fmaxf(d[2], 0.f), msg[grp][mt][1][2 * t]);      \
                    msg[grp][mt][1][2 * t + 1] = fmaf(                      \
                        x1, fmaxf(d[3], 0.f), msg[grp][mt][1][2 * t + 1]);  \
                }                                                           \
            }                                                               \
        }                                                                   \
    } while (0)

    for (int tile = gw; tile < ntiles; tile += gstride) {
        u32 Ah[2][2][2][4];   // [sub][mt][kk][4]

#pragma unroll
        for (int sub = 0; sub < 2; sub++) {
            // ============ phase 1: thread = edge ============
            int e = (tile << 6) + (sub << 5) + lane;
            bool valid = e < E;
            float vx = 0.f, vy = 0.f, vz = 0.f, ea = 0.f;
            int si = 0, di = -1;
            if (valid) {
                si = srcp[e];
                di = dstp[e];
                float px = positions[si * 3 + 0], py = positions[si * 3 + 1],
                      pz = positions[si * 3 + 2];
                float qx = positions[di * 3 + 0], qy = positions[di * 3 + 1],
                      qz = positions[di * 3 + 2];
                vx = qx - px + shifts[e * 3 + 0];
                vy = qy - py + shifts[e * 3 + 1];
                vz = qz - pz + shifts[e * 3 + 2];
                ea = edge_attr[e];
            }
            dstw[sub * 32 + lane] = valid ? di : -1;
            float len = sqrtf(vx * vx + vy * vy + vz * vz);

            float h1[32];
#pragma unroll
            for (int k = 0; k < 32; k++) {
                float a = smf[F_B1 + k];
                a = fmaf(vx, smf[F_W1 + 0 * 32 + k], a);
                a = fmaf(vy, smf[F_W1 + 1 * 32 + k], a);
                a = fmaf(vz, smf[F_W1 + 2 * 32 + k], a);
                a = fmaf(len, smf[F_W1 + 3 * 32 + k], a);
                a = fmaf(ea, smf[F_W1 + 4 * 32 + k], a);
                h1[k] = fmaxf(a, 0.f);
            }

            // h1 -> fp16 2-split A row
            {
                char* arow = arow_base + lane * A_STRIDE;
#pragma unroll
                for (int t = 0; t < 16; t++) {
                    float v0 = h1[2 * t], v1 = h1[2 * t + 1];
                    __half2 hh = __floats2half2_rn(v0, v1);
                    float2 fb = __half22float2(hh);
                    __half2 ll = __floats2half2_rn(v0 - fb.x, v1 - fb.y);
                    *(u32*)(arow + 4 * t) = *(u32*)&hh;
                    *(u32*)(arow + 64 + 4 * t) = *(u32*)&ll;
                }
            }
            // x[src] -> xs
            if (valid) {
                const float4* xr = (const float4*)(g_x + (size_t)si * 32);
                float* xd = xw + (sub * 32 + lane) * 33;
#pragma unroll
                for (int t = 0; t < 8; t++) {
                    float4 v = xr[t];
                    xd[4 * t + 0] = v.x;
                    xd[4 * t + 1] = v.y;
                    xd[4 * t + 2] = v.z;
                    xd[4 * t + 3] = v.w;
                }
            }
            __syncwarp();

            // ============ h2 GEMM: h2 = relu(h1 @ W2 + b2) ============
            {
                u32 A1h[2][2][4], A1l[2][2][4];
#pragma unroll
                for (int mt = 0; mt < 2; mt++)
#pragma unroll
                    for (int kk = 0; kk < 2; kk++) {
                        u32 a = aw + (u32)((mt * 16 + rowoff) * A_STRIDE) +
                                (u32)(kk * 32 + colb16);
                        ldsm_x4(A1h[mt][kk], a);
                        ldsm_x4(A1l[mt][kk], a + 64);
                    }

#pragma unroll
                for (int ni = 0; ni < 2; ni++) {
                    u32 bch = sb + OFF_W2H + (u32)(ni * 32 + colb16);
                    u32 bcl = sb + OFF_W2L + (u32)(ni * 32 + colb16);
                    u32 b0h[4], b1h[4], b0l[4], b1l[4];
                    ldsm_x4t(b0h, bch + (u32)(rowoff * W2_STRIDE));
                    ldsm_x4t(b1h, bch + (u32)((rowoff + 16) * W2_STRIDE));
                    ldsm_x4t(b0l, bcl + (u32)(rowoff * W2_STRIDE));
                    ldsm_x4t(b1l, bcl + (u32)((rowoff + 16) * W2_STRIDE));

                    float a2[2][2][4];
#pragma unroll
                    for (int n8l = 0; n8l < 2; n8l++) {
                        float2 bb = *(const float2*)(smf + F_B2 +
                                                     (ni * 2 + n8l) * 8 +
                                                     2 * tq);
#pragma unroll
                        for (int mt = 0; mt < 2; mt++) {
                            a2[mt][n8l][0] = bb.x;
                            a2[mt][n8l][1] = bb.y;
                            a2[mt][n8l][2] = bb.x;
                            a2[mt][n8l][3] = bb.y;
                        }
                    }
                    mma_f16(a2[0][0], A1h[0][0], b0h[0], b0h[1]);
                    mma_f16(a2[0][1], A1h[0][0], b0h[2], b0h[3]);
                    mma_f16(a2[1][0], A1h[1][0], b0h[0], b0h[1]);
                    mma_f16(a2[1][1], A1h[1][0], b0h[2], b0h[3]);
                    mma_f16(a2[0][0], A1h[0][1], b1h[0], b1h[1]);
                    mma_f16(a2[0][1], A1h[0][1], b1h[2], b1h[3]);
                    mma_f16(a2[1][0], A1h[1][1], b1h[0], b1h[1]);
                    mma_f16(a2[1][1], A1h[1][1], b1h[2], b1h[3]);
                    mma_f16(a2[0][0], A1l[0][0], b0h[0], b0h[1]);
                    mma_f16(a2[0][1], A1l[0][0], b0h[2], b0h[3]);
                    mma_f16(a2[1][0], A1l[1][0], b0h[0], b0h[1]);
                    mma_f16(a2[1][1], A1l[1][0], b0h[2], b0h[3]);
                    mma_f16(a2[0][0], A1l[0][1], b1h[0], b1h[1]);
                    mma_f16(a2[0][1], A1l[0][1], b1h[2], b1h[3]);
                    mma_f16(a2[1][0], A1l[1][1], b1h[0], b1h[1]);
                    mma_f16(a2[1][1], A1l[1][1], b1h[2], b1h[3]);
                    mma_f16(a2[0][0], A1h[0][0], b0l[0], b0l[1]);
                    mma_f16(a2[0][1], A1h[0][0], b0l[2], b0l[3]);
                    mma_f16(a2[1][0], A1h[1][0], b0l[0], b0l[1]);
                    mma_f16(a2[1][1], A1h[1][0], b0l[2], b0l[3]);
                    mma_f16(a2[0][0], A1h[0][1], b1l[0], b1l[1]);
                    mma_f16(a2[0][1], A1h[0][1], b1l[2], b1l[3]);
                    mma_f16(a2[1][0], A1h[1][1], b1l[0], b1l[1]);
                    mma_f16(a2[1][1], A1h[1][1], b1l[2], b1l[3]);

                    // write-out: relu -> fp16 high
#pragma unroll
                    for (int mt = 0; mt < 2; mt++)
#pragma unroll
                        for (int n8l = 0; n8l < 2; n8l++) {
                            int cbyte = ((ni * 2 + n8l) * 8 + 2 * tq) * 2;
                            char* r0p = arow_base +
                                        (mt * 16 + g) * A_STRIDE + cbyte;
                            char* r8p = r0p + 8 * A_STRIDE;
                            const float* d = a2[mt][n8l];
                            float f0 = fmaxf(d[0], 0.f), f1 = fmaxf(d[1], 0.f);
                            float f2 = fmaxf(d[2], 0.f), f3 = fmaxf(d[3], 0.f);
                            __half2 h0 = __floats2half2_rn(f0, f1);
                            __half2 h8 = __floats2half2_rn(f2, f3);
                            *(u32*)r0p = *(u32*)&h0;
                            *(u32*)r8p = *(u32*)&h8;
                        }
                }
            }
            __syncwarp();

            // hold this sub-tile's A fragments in registers
#pragma unroll
            for (int mt = 0; mt < 2; mt++)
#pragma unroll
                for (int kk = 0; kk < 2; kk++) {
                    u32 a = aw + (u32)((mt * 16 + rowoff) * A_STRIDE) +
                            (u32)(kk * 32 + colb16);
                    ldsm_x4(Ah[sub][mt][kk], a);
                }
            __syncwarp();
        }

        float msg[2][2][2][8];
#pragma unroll
        for (int a = 0; a < 2; a++)
#pragma unroll
            for (int m = 0; m < 2; m++)
#pragma unroll
                for (int hf = 0; hf < 2; hf++)
#pragma unroll
                    for (int t = 0; t < 8; t++) msg[a][m][hf][t] = 0.f;

        // ======== 32 chunks of n=32, B double-buffered, 4 m-tiles ========
        u32 bbA[4][4], bbB[4][4];
        LOADB(bbA, 0);
#pragma unroll 1
        for (int c = 0; c < 32; c += 2) {
            LOADB(bbB, c + 1);
            CHUNK_BODY(bbA, c);
            if (c + 2 < 32) LOADB(bbA, c + 2);
            CHUNK_BODY(bbB, c + 1);
        }

        // ================= scatter (vector atomics) =================
#pragma unroll
        for (int grp = 0; grp < 2; grp++)
#pragma unroll
            for (int mt = 0; mt < 2; mt++)
#pragma unroll
                for (int hf = 0; hf < 2; hf++) {
                    int row = grp * 32 + mt * 16 + hf * 8 + g;
                    int d = dstw[row];
                    if (d >= 0) {
                        float* ap = g_agg + (size_t)d * 32 + 2 * tq;
#pragma unroll
                        for (int t = 0; t < 4; t++)
                            red_v2(ap + 8 * t, msg[grp][mt][hf][2 * t],
                                   msg[grp][mt][hf][2 * t + 1]);
                    }
                }
        __syncwarp();
    }
#undef LOADB
#undef CHUNK_BODY
}

// ---------------------------------------------------------------------------
__global__ void node_kernel(const float* __restrict__ conv_b, int N) {
    int idx = blockIdx.x * blockDim.x + threadIdx.x;
    if (idx < N * 32) {
        float v = g_agg[idx] + conv_b[idx & 31];
        g_x[idx] += fmaxf(v, 0.f);
        g_agg[idx] = 0.f;
    }
}

__global__ void pool_kernel(const int* __restrict__ batch_ids, int N) {
    int idx = blockIdx.x * blockDim.x + threadIdx.x;
    if (idx < N * 32) {
        int n = idx >> 5, k = idx & 31;
        int b = batch_ids[n];
        atomicAdd(&g_pooled[b * 32 + k], g_x[idx]);
        if (k == 0) atomicAdd(&g_counts[b], 1.f);
    }
}

__device__ __forceinline__ float selu_f(float x) {
    const float alpha = 1.6732632423543772f;
    const float scale = 1.0507009873554805f;
    return x > 0.f ? scale * x : scale * alpha * expm1f(x);
}

__global__ void mlp_kernel(const float* __restrict__ W1,
                           const float* __restrict__ b1,
                           const float* __restrict__ W2,
                           const float* __restrict__ b2,
                           const float* __restrict__ W3,
                           const float* __restrict__ b3,
                           const float* __restrict__ W4,
                           const float* __restrict__ b4,
                           float* __restrict__ out) {
    __shared__ float sbuf[32][280];
    int warp = threadIdx.x >> 5, lane = threadIdx.x & 31;
    int b = blockIdx.x * 32 + warp;
    if (b >= BATCH) return;
    float* buf = sbuf[warp];

    float cnt = fmaxf(g_counts[b], 1.f);
    buf[lane] = g_pooled[b * 32 + lane] / cnt;
    __syncwarp();

#pragma unroll
    for (int r = 0; r < 4; r++) {
        int o = lane + 32 * r;
        float a = b1[o];
        for (int k = 0; k < 32; k++) a = fmaf(buf[k], W1[k * 128 + o], a);
        buf[32 + o] = selu_f(a);
    }
    __syncwarp();
#pragma unroll
    for (int r = 0; r < 2; r++) {
        int o = lane + 32 * r;
        float a = b2[o];
        for (int k = 0; k < 128; k++) a = fmaf(buf[32 + k], W2[k * 64 + o], a);
        buf[160 + o] = selu_f(a);
    }
    __syncwarp();
    {
        int o = lane;
        float a = b3[o];
        for (int k = 0; k < 64; k++) a = fmaf(buf[160 + k], W3[k * 32 + o], a);
        buf[224 + o] = selu_f(a);
    }
    __syncwarp();
    if (lane < 21) {
        float a = b4[lane];
        for (int k = 0; k < 32; k++) a = fmaf(buf[224 + k], W4[k * 21 + lane], a);
        buf[256 + lane] = a;
    }
    __syncwarp();
    for (int r = lane; r < 36; r += 32) out[b * 36 + r] = buf[256 + c_IDX[r]];
}

// ---------------------------------------------------------------------------
extern "C" void kernel_launch(void* const* d_in, const int* in_sizes, int n_in,
                              void* d_out, int out_size) {
    const float* node_attrs = (const float*)d_in[0];
    const float* positions = (const float*)d_in[1];
    const float* shifts = (const float*)d_in[2];
    const float* edge_attr = (const float*)d_in[3];
    const int* edge_index = (const int*)d_in[4];
    const int* batch_ids = (const int*)d_in[5];
    const float* embed_W = (const float*)d_in[6];
    const float* embed_b = (const float*)d_in[7];
    const float* e_W1 = (const float*)d_in[8];
    const float* e_b1 = (const float*)d_in[9];
    const float* e_W2 = (const float*)d_in[10];
    const float* e_b2 = (const float*)d_in[11];
    const float* e_W3 = (const float*)d_in[12];
    const float* e_b3 = (const float*)d_in[13];
    const float* conv_b = (const float*)d_in[14];
    const float* h_W1 = (const float*)d_in[15];
    const float* h_b1 = (const float*)d_in[16];
    const float* h_W2 = (const float*)d_in[17];
    const float* h_b2 = (const float*)d_in[18];
    const float* h_W3 = (const float*)d_in[19];
    const float* h_b3 = (const float*)d_in[20];
    const float* h_W4 = (const float*)d_in[21];
    const float* h_b4 = (const float*)d_in[22];

    int N = in_sizes[0];
    int E = in_sizes[3];
    if (N > NMAX) N = NMAX;
    if (E > EMAX) E = EMAX;

    cudaFuncSetAttribute(edge_kernel,
                         cudaFuncAttributeMaxDynamicSharedMemorySize,
                         SMEM_TOTAL);

    int tot = N * 32;
    int blk = 256;
    init_kernel<<<(tot + blk - 1) / blk, blk>>>(node_attrs, embed_W, embed_b, N);

    for (int l = 0; l < 3; l++) {
        edge_kernel<<<148, NTHREADS, SMEM_TOTAL>>>(
            positions, shifts, edge_attr, edge_index, e_W1 + l * 160,
            e_b1 + l * 32, e_W2 + l * 1024, e_b2 + l * 32, e_W3 + l * 32768,
            e_b3 + l * 1024, E);
        node_kernel<<<(tot + blk - 1) / blk, blk>>>(conv_b + l * 32, N);
    }

    pool_kernel<<<(tot + blk - 1) / blk, blk>>>(batch_ids, N);
    mlp_kernel<<<2, 1024>>>(h_W1, h_b1, h_W2, h_b2, h_W3, h_b3, h_W4, h_b4,
                            (float*)d_out);
}

// round 10
// speedup vs baseline: 1.1459x; 1.1459x over previous
#include <cuda_runtime.h>
#include <cuda_fp16.h>
#include <math.h>

// ---------------------------------------------------------------------------
// NNConvNet fused GNN — R9: R7 structure (32 edges/warp, 16 mma/chunk,
// scalar epilogue, B double-buffered) + red.global.add.v2.f32 scatter
// + 16 warps/CTA (512 threads, 128-reg cap — R7 compiled at exactly 128).
// ---------------------------------------------------------------------------

#define NMAX 20000
#define EMAX 320000
#define BATCH 64
#define NWARPS 16
#define NTHREADS (NWARPS * 32)

typedef unsigned int u32;
typedef unsigned short u16;

__device__ float g_x[NMAX * 32];
__device__ float g_agg[NMAX * 32];
__device__ float g_pooled[BATCH * 32];
__device__ float g_counts[BATCH];

__constant__ int c_IDX[36] = {
    0, 1, 2,  3,  4,  5,
    1, 6, 7,  8,  9,  10,
    2, 7, 11, 12, 13, 14,
    3, 8, 12, 15, 16, 17,
    4, 9, 13, 16, 18, 19,
    5, 10,14, 17, 19, 20};

// ---------------- smem layout ----------------
// floats:
#define F_W1 0        // 160
#define F_B1 160      // 32
#define F_B2 192      // 32
#define F_B3S 224     // 1024 (ends 1248 floats = 4992 B)
// bytes:
#define OFF_W2H 4992                  // 32 rows * 80 B = 2560
#define OFF_W2L 7552                  // 2560 (ends 10112)
#define OFF_DSTS 10112                // 16 warps * 32 int = 2048 (ends 12160)
#define OFF_XS 12160                  // 16*32*33*4 = 67584 (ends 79744)
#define OFF_A 79744                   // 16*32*144 = 73728 (ends 153472)
#define OFF_B 153472                  // 32*2064 = 66048 (ends 219520)
#define A_STRIDE 144
#define B_STRIDE 2064
#define W2_STRIDE 80
#define SMEM_TOTAL 219520

// ---------------- PTX helpers ----------------
__device__ __forceinline__ u32 smem_u32(const void* p) {
    u32 a;
    asm("{ .reg .u64 t; cvta.to.shared.u64 t, %1; cvt.u32.u64 %0, t; }"
        : "=r"(a) : "l"(p));
    return a;
}
__device__ __forceinline__ void ldsm_x4(u32* r, u32 addr) {
    asm volatile(
        "ldmatrix.sync.aligned.m8n8.x4.shared.b16 {%0,%1,%2,%3}, [%4];"
        : "=r"(r[0]), "=r"(r[1]), "=r"(r[2]), "=r"(r[3]) : "r"(addr));
}
__device__ __forceinline__ void ldsm_x4t(u32* r, u32 addr) {
    asm volatile(
        "ldmatrix.sync.aligned.m8n8.x4.trans.shared.b16 {%0,%1,%2,%3}, [%4];"
        : "=r"(r[0]), "=r"(r[1]), "=r"(r[2]), "=r"(r[3]) : "r"(addr));
}
__device__ __forceinline__ void mma_f16(float* d, const u32* a, u32 b0,
                                        u32 b1) {
    asm volatile(
        "mma.sync.aligned.m16n8k16.row.col.f32.f16.f16.f32 "
        "{%0,%1,%2,%3}, {%4,%5,%6,%7}, {%8,%9}, {%0,%1,%2,%3};"
        : "+f"(d[0]), "+f"(d[1]), "+f"(d[2]), "+f"(d[3])
        : "r"(a[0]), "r"(a[1]), "r"(a[2]), "r"(a[3]), "r"(b0), "r"(b1));
}
__device__ __forceinline__ void red_v2(float* ap, float m0, float m1) {
    asm volatile("red.global.add.v2.f32 [%0], {%1, %2};"
                 :: "l"(ap), "f"(m0), "f"(m1) : "memory");
}

// ---------------------------------------------------------------------------
__global__ void init_kernel(const float* __restrict__ node_attrs,
                            const float* __restrict__ embW,
                            const float* __restrict__ embB, int N) {
    int idx = blockIdx.x * blockDim.x + threadIdx.x;
    if (idx < N * 32) {
        int k = idx & 31;
        g_x[idx] = fmaf(node_attrs[idx >> 5], embW[k], embB[k]);
        g_agg[idx] = 0.f;
    }
    if (idx < BATCH * 32) g_pooled[idx] = 0.f;
    if (idx < BATCH) g_counts[idx] = 0.f;
}

// ---------------------------------------------------------------------------
__global__ void __launch_bounds__(NTHREADS, 1)
edge_kernel(const float* __restrict__ positions,
            const float* __restrict__ shifts,
            const float* __restrict__ edge_attr,
            const int* __restrict__ eidx,
            const float* __restrict__ W1, const float* __restrict__ b1,
            const float* __restrict__ W2, const float* __restrict__ b2,
            const float* __restrict__ W3, const float* __restrict__ b3,
            int E) {
    extern __shared__ float smf[];
    char* smc = (char*)smf;
    const u32 sb = smem_u32(smf);
    const int tid = threadIdx.x;
    const int lane = tid & 31;
    const int warp = tid >> 5;

    // ---- stage B = fp16(W3) in [j][n] layout ----
    for (int i = tid; i < 32768; i += NTHREADS) {
        int j = i >> 10, col = i & 1023;
        __half h = __float2half_rn(W3[i]);
        *(u16*)(smc + OFF_B + j * B_STRIDE + col * 2) = *(u16*)&h;
    }
    // ---- W2 fp16 2-split [j][n] ----
    for (int i = tid; i < 1024; i += NTHREADS) {
        int j = i >> 5, n = i & 31;
        float w = W2[i];
        __half hh = __float2half_rn(w);
        __half ll = __float2half_rn(w - __half2float(hh));
        *(u16*)(smc + OFF_W2H + j * W2_STRIDE + n * 2) = *(u16*)&hh;
        *(u16*)(smc + OFF_W2L + j * W2_STRIDE + n * 2) = *(u16*)&ll;
        smf[F_B3S + i] = b3[i];
    }
    if (tid < 160) smf[F_W1 + tid] = W1[tid];
    if (tid < 32) {
        smf[F_B1 + tid] = b1[tid];
        smf[F_B2 + tid] = b2[tid];
    }
    __syncthreads();

    const int g = lane >> 2;     // fragment row group
    const int tq = lane & 3;     // fragment col group
    char* arow_base = smc + OFF_A + (warp * 32) * A_STRIDE;
    const u32 aw = sb + OFF_A + (u32)(warp * 32) * A_STRIDE;
    float* xw = (float*)(smc + OFF_XS) + warp * (32 * 33);
    int* dstw = (int*)(smc + OFF_DSTS) + warp * 32;

    const int rowoff = ((lane >> 3) & 1) * 8 + (lane & 7);
    const int colb16 = (lane >> 4) * 16;

    const int* srcp = eidx;
    const int* dstp = eidx + E;
    const int ntiles = (E + 31) >> 5;
    const int gw = blockIdx.x * NWARPS + warp;
    const int gstride = gridDim.x * NWARPS;

#define LOADB(FR, C)                                                        \
    do {                                                                    \
        u32 _bc = sb + OFF_B + (u32)((C) * 64 + colb16);                    \
        ldsm_x4t(FR[0], _bc + (u32)(rowoff * B_STRIDE));                    \
        ldsm_x4t(FR[1], _bc + (u32)((rowoff + 16) * B_STRIDE));             \
        ldsm_x4t(FR[2], _bc + 32 + (u32)(rowoff * B_STRIDE));               \
        ldsm_x4t(FR[3], _bc + 32 + (u32)((rowoff + 16) * B_STRIDE));        \
    } while (0)

#define CHUNK_BODY(BB, C)                                                   \
    do {                                                                    \
        const int _cb = (C) * 32;                                           \
        float acc[2][4][4];                                                 \
        _Pragma("unroll") for (int n8 = 0; n8 < 4; n8++) {                  \
            float2 bv =                                                     \
                *(const float2*)(smf + F_B3S + _cb + n8 * 8 + 2 * tq);      \
            _Pragma("unroll") for (int mt = 0; mt < 2; mt++) {              \
                acc[mt][n8][0] = bv.x;                                      \
                acc[mt][n8][1] = bv.y;                                      \
                acc[mt][n8][2] = bv.x;                                      \
                acc[mt][n8][3] = bv.y;                                      \
            }                                                               \
        }                                                                   \
        mma_f16(acc[0][0], Ah[0][0], BB[0][0], BB[0][1]);                   \
        mma_f16(acc[0][1], Ah[0][0], BB[0][2], BB[0][3]);                   \
        mma_f16(acc[1][0], Ah[1][0], BB[0][0], BB[0][1]);                   \
        mma_f16(acc[1][1], Ah[1][0], BB[0][2], BB[0][3]);                   \
        mma_f16(acc[0][2], Ah[0][0], BB[2][0], BB[2][1]);                   \
        mma_f16(acc[0][3], Ah[0][0], BB[2][2], BB[2][3]);                   \
        mma_f16(acc[1][2], Ah[1][0], BB[2][0], BB[2][1]);                   \
        mma_f16(acc[1][3], Ah[1][0], BB[2][2], BB[2][3]);                   \
        mma_f16(acc[0][0], Ah[0][1], BB[1][0], BB[1][1]);                   \
        mma_f16(acc[0][1], Ah[0][1], BB[1][2], BB[1][3]);                   \
        mma_f16(acc[1][0], Ah[1][1], BB[1][0], BB[1][1]);                   \
        mma_f16(acc[1][1], Ah[1][1], BB[1][2], BB[1][3]);                   \
        mma_f16(acc[0][2], Ah[0][1], BB[3][0], BB[3][1]);                   \
        mma_f16(acc[0][3], Ah[0][1], BB[3][2], BB[3][3]);                   \
        mma_f16(acc[1][2], Ah[1][1], BB[3][0], BB[3][1]);                   \
        mma_f16(acc[1][3], Ah[1][1], BB[3][2], BB[3][3]);                   \
        _Pragma("unroll") for (int mt = 0; mt < 2; mt++) {                  \
            float x0 = xw[(mt * 16 + g) * 33 + (C)];                        \
            float x1 = xw[(mt * 16 + 8 + g) * 33 + (C)];                    \
            _Pragma("unroll") for (int t = 0; t < 4; t++) {                 \
                const float* d = acc[mt][t];                                \
                msg[mt][0][2 * t] =                                         \
                    fmaf(x0, fmaxf(d[0], 0.f), msg[mt][0][2 * t]);          \
                msg[mt][0][2 * t + 1] =                                     \
                    fmaf(x0, fmaxf(d[1], 0.f), msg[mt][0][2 * t + 1]);      \
                msg[mt][1][2 * t] =                                         \
                    fmaf(x1, fmaxf(d[2], 0.f), msg[mt][1][2 * t]);          \
                msg[mt][1][2 * t + 1] =                                     \
                    fmaf(x1, fmaxf(d[3], 0.f), msg[mt][1][2 * t + 1]);      \
            }                                                               \
        }                                                                   \
    } while (0)

    for (int tile = gw; tile < ntiles; tile += gstride) {
        // ================= phase 1: thread = edge, h1 only =================
        int e = (tile << 5) + lane;
        bool valid = e < E;
        float vx = 0.f, vy = 0.f, vz = 0.f, ea = 0.f;
        int si = 0, di = -1;
        if (valid) {
            si = srcp[e];
            di = dstp[e];
            float px = positions[si * 3 + 0], py = positions[si * 3 + 1],
                  pz = positions[si * 3 + 2];
            float qx = positions[di * 3 + 0], qy = positions[di * 3 + 1],
                  qz = positions[di * 3 + 2];
            vx = qx - px + shifts[e * 3 + 0];
            vy = qy - py + shifts[e * 3 + 1];
            vz = qz - pz + shifts[e * 3 + 2];
            ea = edge_attr[e];
        }
        dstw[lane] = valid ? di : -1;
        float len = sqrtf(vx * vx + vy * vy + vz * vz);

        float h1[32];
#pragma unroll
        for (int k = 0; k < 32; k++) {
            float a = smf[F_B1 + k];
            a = fmaf(vx, smf[F_W1 + 0 * 32 + k], a);
            a = fmaf(vy, smf[F_W1 + 1 * 32 + k], a);
            a = fmaf(vz, smf[F_W1 + 2 * 32 + k], a);
            a = fmaf(len, smf[F_W1 + 3 * 32 + k], a);
            a = fmaf(ea, smf[F_W1 + 4 * 32 + k], a);
            h1[k] = fmaxf(a, 0.f);
        }

        // h1 -> fp16 2-split A row [h1h(32)|h1l(32)]
        {
            char* arow = arow_base + lane * A_STRIDE;
#pragma unroll
            for (int t = 0; t < 16; t++) {
                float v0 = h1[2 * t], v1 = h1[2 * t + 1];
                __half2 hh = __floats2half2_rn(v0, v1);
                float2 fb = __half22float2(hh);
                __half2 ll = __floats2half2_rn(v0 - fb.x, v1 - fb.y);
                *(u32*)(arow + 4 * t) = *(u32*)&hh;
                *(u32*)(arow + 64 + 4 * t) = *(u32*)&ll;
            }
        }
        // x[src] -> xs
        if (valid) {
            const float4* xr = (const float4*)(g_x + (size_t)si * 32);
            float* xd = xw + lane * 33;
#pragma unroll
            for (int t = 0; t < 8; t++) {
                float4 v = xr[t];
                xd[4 * t + 0] = v.x;
                xd[4 * t + 1] = v.y;
                xd[4 * t + 2] = v.z;
                xd[4 * t + 3] = v.w;
            }
        }
        __syncwarp();

        // ================= h2 GEMM: h2 = relu(h1 @ W2 + b2) =================
        {
            u32 A1h[2][2][4], A1l[2][2][4];
#pragma unroll
            for (int mt = 0; mt < 2; mt++)
#pragma unroll
                for (int kk = 0; kk < 2; kk++) {
                    u32 a = aw + (u32)((mt * 16 + rowoff) * A_STRIDE) +
                            (u32)(kk * 32 + colb16);
                    ldsm_x4(A1h[mt][kk], a);
                    ldsm_x4(A1l[mt][kk], a + 64);
                }

#pragma unroll
            for (int ni = 0; ni < 2; ni++) {
                u32 bch = sb + OFF_W2H + (u32)(ni * 32 + colb16);
                u32 bcl = sb + OFF_W2L + (u32)(ni * 32 + colb16);
                u32 b0h[4], b1h[4], b0l[4], b1l[4];
                ldsm_x4t(b0h, bch + (u32)(rowoff * W2_STRIDE));
                ldsm_x4t(b1h, bch + (u32)((rowoff + 16) * W2_STRIDE));
                ldsm_x4t(b0l, bcl + (u32)(rowoff * W2_STRIDE));
                ldsm_x4t(b1l, bcl + (u32)((rowoff + 16) * W2_STRIDE));

                float a2[2][2][4];
#pragma unroll
                for (int n8l = 0; n8l < 2; n8l++) {
                    float2 bb = *(const float2*)(smf + F_B2 +
                                                 (ni * 2 + n8l) * 8 + 2 * tq);
#pragma unroll
                    for (int mt = 0; mt < 2; mt++) {
                        a2[mt][n8l][0] = bb.x;
                        a2[mt][n8l][1] = bb.y;
                        a2[mt][n8l][2] = bb.x;
                        a2[mt][n8l][3] = bb.y;
                    }
                }
                mma_f16(a2[0][0], A1h[0][0], b0h[0], b0h[1]);
                mma_f16(a2[0][1], A1h[0][0], b0h[2], b0h[3]);
                mma_f16(a2[1][0], A1h[1][0], b0h[0], b0h[1]);
                mma_f16(a2[1][1], A1h[1][0], b0h[2], b0h[3]);
                mma_f16(a2[0][0], A1h[0][1], b1h[0], b1h[1]);
                mma_f16(a2[0][1], A1h[0][1], b1h[2], b1h[3]);
                mma_f16(a2[1][0], A1h[1][1], b1h[0], b1h[1]);
                mma_f16(a2[1][1], A1h[1][1], b1h[2], b1h[3]);
                mma_f16(a2[0][0], A1l[0][0], b0h[0], b0h[1]);
                mma_f16(a2[0][1], A1l[0][0], b0h[2], b0h[3]);
                mma_f16(a2[1][0], A1l[1][0], b0h[0], b0h[1]);
                mma_f16(a2[1][1], A1l[1][0], b0h[2], b0h[3]);
                mma_f16(a2[0][0], A1l[0][1], b1h[0], b1h[1]);
                mma_f16(a2[0][1], A1l[0][1], b1h[2], b1h[3]);
                mma_f16(a2[1][0], A1l[1][1], b1h[0], b1h[1]);
                mma_f16(a2[1][1], A1l[1][1], b1h[2], b1h[3]);
                mma_f16(a2[0][0], A1h[0][0], b0l[0], b0l[1]);
                mma_f16(a2[0][1], A1h[0][0], b0l[2], b0l[3]);
                mma_f16(a2[1][0], A1h[1][0], b0l[0], b0l[1]);
                mma_f16(a2[1][1], A1h[1][0], b0l[2], b0l[3]);
                mma_f16(a2[0][0], A1h[0][1], b1l[0], b1l[1]);
                mma_f16(a2[0][1], A1h[0][1], b1l[2], b1l[3]);
                mma_f16(a2[1][0], A1h[1][1], b1l[0], b1l[1]);
                mma_f16(a2[1][1], A1h[1][1], b1l[2], b1l[3]);

                // write-out: relu -> fp16 (high only; W3 GEMM single-split)
#pragma unroll
                for (int mt = 0; mt < 2; mt++)
#pragma unroll
                    for (int n8l = 0; n8l < 2; n8l++) {
                        int cbyte = ((ni * 2 + n8l) * 8 + 2 * tq) * 2;
                        char* r0p =
                            arow_base + (mt * 16 + g) * A_STRIDE + cbyte;
                        char* r8p = r0p + 8 * A_STRIDE;
                        const float* d = a2[mt][n8l];
                        float f0 = fmaxf(d[0], 0.f), f1 = fmaxf(d[1], 0.f);
                        float f2 = fmaxf(d[2], 0.f), f3 = fmaxf(d[3], 0.f);
                        __half2 h0 = __floats2half2_rn(f0, f1);
                        __half2 h8 = __floats2half2_rn(f2, f3);
                        *(u32*)r0p = *(u32*)&h0;
                        *(u32*)r8p = *(u32*)&h8;
                    }
            }
        }
        __syncwarp();

        // ================= main A fragments (h2 fp16, single split) ========
        u32 Ah[2][2][4];
#pragma unroll
        for (int mt = 0; mt < 2; mt++)
#pragma unroll
            for (int kk = 0; kk < 2; kk++) {
                u32 a = aw + (u32)((mt * 16 + rowoff) * A_STRIDE) +
                        (u32)(kk * 32 + colb16);
                ldsm_x4(Ah[mt][kk], a);
            }

        float msg[2][2][8];
#pragma unroll
        for (int a = 0; a < 2; a++)
#pragma unroll
            for (int hf = 0; hf < 2; hf++)
#pragma unroll
                for (int t = 0; t < 8; t++) msg[a][hf][t] = 0.f;

        // ============ 32 chunks of n=32 (chunk == h), B prefetched ==========
        u32 bbA[4][4], bbB[4][4];
        LOADB(bbA, 0);
#pragma unroll 1
        for (int c = 0; c < 32; c += 2) {
            LOADB(bbB, c + 1);
            CHUNK_BODY(bbA, c);
            if (c + 2 < 32) LOADB(bbA, c + 2);
            CHUNK_BODY(bbB, c + 1);
        }

        // ================= scatter (vector atomics) =================
#pragma unroll
        for (int mt = 0; mt < 2; mt++)
#pragma unroll
            for (int hf = 0; hf < 2; hf++) {
                int row = mt * 16 + hf * 8 + g;
                int d = dstw[row];
                if (d >= 0) {
                    float* ap = g_agg + (size_t)d * 32 + 2 * tq;
#pragma unroll
                    for (int t = 0; t < 4; t++)
                        red_v2(ap + 8 * t, msg[mt][hf][2 * t],
                               msg[mt][hf][2 * t + 1]);
                }
            }
        __syncwarp();
    }
#undef LOADB
#undef CHUNK_BODY
}

// ---------------------------------------------------------------------------
__global__ void node_kernel(const float* __restrict__ conv_b, int N) {
    int idx = blockIdx.x * blockDim.x + threadIdx.x;
    if (idx < N * 32) {
        float v = g_agg[idx] + conv_b[idx & 31];
        g_x[idx] += fmaxf(v, 0.f);
        g_agg[idx] = 0.f;
    }
}

__global__ void pool_kernel(const int* __restrict__ batch_ids, int N) {
    int idx = blockIdx.x * blockDim.x + threadIdx.x;
    if (idx < N * 32) {
        int n = idx >> 5, k = idx & 31;
        int b = batch_ids[n];
        atomicAdd(&g_pooled[b * 32 + k], g_x[idx]);
        if (k == 0) atomicAdd(&g_counts[b], 1.f);
    }
}

__device__ __forceinline__ float selu_f(float x) {
    const float alpha = 1.6732632423543772f;
    const float scale = 1.0507009873554805f;
    return x > 0.f ? scale * x : scale * alpha * expm1f(x);
}

__global__ void mlp_kernel(const float* __restrict__ W1,
                           const float* __restrict__ b1,
                           const float* __restrict__ W2,
                           const float* __restrict__ b2,
                           const float* __restrict__ W3,
                           const float* __restrict__ b3,
                           const float* __restrict__ W4,
                           const float* __restrict__ b4,
                           float* __restrict__ out) {
    __shared__ float sbuf[32][280];
    int warp = threadIdx.x >> 5, lane = threadIdx.x & 31;
    int b = blockIdx.x * 32 + warp;
    if (b >= BATCH) return;
    float* buf = sbuf[warp];

    float cnt = fmaxf(g_counts[b], 1.f);
    buf[lane] = g_pooled[b * 32 + lane] / cnt;
    __syncwarp();

#pragma unroll
    for (int r = 0; r < 4; r++) {
        int o = lane + 32 * r;
        float a = b1[o];
        for (int k = 0; k < 32; k++) a = fmaf(buf[k], W1[k * 128 + o], a);
        buf[32 + o] = selu_f(a);
    }
    __syncwarp();
#pragma unroll
    for (int r = 0; r < 2; r++) {
        int o = lane + 32 * r;
        float a = b2[o];
        for (int k = 0; k < 128; k++) a = fmaf(buf[32 + k], W2[k * 64 + o], a);
        buf[160 + o] = selu_f(a);
    }
    __syncwarp();
    {
        int o = lane;
        float a = b3[o];
        for (int k = 0; k < 64; k++) a = fmaf(buf[160 + k], W3[k * 32 + o], a);
        buf[224 + o] = selu_f(a);
    }
    __syncwarp();
    if (lane < 21) {
        float a = b4[lane];
        for (int k = 0; k < 32; k++) a = fmaf(buf[224 + k], W4[k * 21 + lane], a);
        buf[256 + lane] = a;
    }
    __syncwarp();
    for (int r = lane; r < 36; r += 32) out[b * 36 + r] = buf[256 + c_IDX[r]];
}

// ---------------------------------------------------------------------------
extern "C" void kernel_launch(void* const* d_in, const int* in_sizes, int n_in,
                              void* d_out, int out_size) {
    const float* node_attrs = (const float*)d_in[0];
    const float* positions = (const float*)d_in[1];
    const float* shifts = (const float*)d_in[2];
    const float* edge_attr = (const float*)d_in[3];
    const int* edge_index = (const int*)d_in[4];
    const int* batch_ids = (const int*)d_in[5];
    const float* embed_W = (const float*)d_in[6];
    const float* embed_b = (const float*)d_in[7];
    const float* e_W1 = (const float*)d_in[8];
    const float* e_b1 = (const float*)d_in[9];
    const float* e_W2 = (const float*)d_in[10];
    const float* e_b2 = (const float*)d_in[11];
    const float* e_W3 = (const float*)d_in[12];
    const float* e_b3 = (const float*)d_in[13];
    const float* conv_b = (const float*)d_in[14];
    const float* h_W1 = (const float*)d_in[15];
    const float* h_b1 = (const float*)d_in[16];
    const float* h_W2 = (const float*)d_in[17];
    const float* h_b2 = (const float*)d_in[18];
    const float* h_W3 = (const float*)d_in[19];
    const float* h_b3 = (const float*)d_in[20];
    const float* h_W4 = (const float*)d_in[21];
    const float* h_b4 = (const float*)d_in[22];

    int N = in_sizes[0];
    int E = in_sizes[3];
    if (N > NMAX) N = NMAX;
    if (E > EMAX) E = EMAX;

    cudaFuncSetAttribute(edge_kernel,
                         cudaFuncAttributeMaxDynamicSharedMemorySize,
                         SMEM_TOTAL);

    int tot = N * 32;
    int blk = 256;
    init_kernel<<<(tot + blk - 1) / blk, blk>>>(node_attrs, embed_W, embed_b, N);

    for (int l = 0; l < 3; l++) {
        edge_kernel<<<148, NTHREADS, SMEM_TOTAL>>>(
            positions, shifts, edge_attr, edge_index, e_W1 + l * 160,
            e_b1 + l * 32, e_W2 + l * 1024, e_b2 + l * 32, e_W3 + l * 32768,
            e_b3 + l * 1024, E);
        node_kernel<<<(tot + blk - 1) / blk, blk>>>(conv_b + l * 32, N);
    }

    pool_kernel<<<(tot + blk - 1) / blk, blk>>>(batch_ids, N);
    mlp_kernel<<<2, 1024>>>(h_W1, h_b1, h_W2, h_b2, h_W3, h_b3, h_W4, h_b4,
                            (float*)d_out);
}